// round 17
// baseline (speedup 1.0000x reference)
#include <cuda_runtime.h>
#include <cuda_fp16.h>
#include <math.h>
#include <stdint.h>

#define EPSV 1e-6f

// ---- smem byte layout (180,992 B total; 1 CTA/SM) ----
#define SAH    0        // 32768: A hi fp16 [64m][256k], 512B rows, byte^(16*(m&7))
#define SA8H   32768    // 17408: Ah8 int8 [64m][272B rows]
#define SA8L   50176    // 17408: Al8 int8 (scaled 2^11)
#define SWRING 67584    // 6 slots x 16KB (Wh fp16 8K | Wl8 4K | Wh8 4K)
#define SBIAS  165888   // 4KB: b1eff,b2,b3,b4
#define SWU    169984   // 5KB: invu[5][256]
#define SROWP  175104   // 256B: invp[64]
#define SMAXS  175360   // 1KB: rowmax[64][4]
#define SD     176384   // 4608B: L5 D[64][18] f32
#define SM_TOTAL 180992

// ---- device scratch ----
__device__ __align__(16) unsigned char g_W1img[32768];    // 2 chunks x 16KB
__device__ __align__(16) unsigned char g_W234img[786432]; // 48 chunks x 16KB
__device__ __align__(16) unsigned char g_W5img[16384];    // Wh 8K | Wl8 4K | Wh8 4K
__device__ __align__(16) float g_latconst[256];
__device__ __align__(16) float g_Wu[1280];
__device__ __align__(16) float g_Winvu[1280];

static __device__ __forceinline__ uint32_t smem_u32(const void* p){
    uint32_t a; asm("{ .reg .u64 t; cvta.to.shared.u64 t, %1; cvt.u32.u64 %0, t; }":"=r"(a):"l"(p)); return a;
}
static __device__ __forceinline__ void cp16(uint32_t d, const void* s){
    asm volatile("cp.async.cg.shared.global [%0], [%1], 16;"::"r"(d),"l"(s));
}
#define CP_COMMIT() asm volatile("cp.async.commit_group;":::"memory")
#define CP_WAIT0()  asm volatile("cp.async.wait_group 0;":::"memory")
#define CP_WAIT4()  asm volatile("cp.async.wait_group 4;":::"memory")

static __device__ __forceinline__ void mma16816(float* c, uint32_t a0, uint32_t a1, uint32_t a2, uint32_t a3,
                                                uint32_t b0, uint32_t b1){
    asm volatile("mma.sync.aligned.m16n8k16.row.col.f32.f16.f16.f32 "
                 "{%0,%1,%2,%3},{%4,%5,%6,%7},{%8,%9},{%0,%1,%2,%3};"
                 : "+f"(c[0]),"+f"(c[1]),"+f"(c[2]),"+f"(c[3])
                 : "r"(a0),"r"(a1),"r"(a2),"r"(a3),"r"(b0),"r"(b1));
}
static __device__ __forceinline__ void mma_s8(int* c, uint32_t a0, uint32_t a1, uint32_t a2, uint32_t a3,
                                              uint32_t b0, uint32_t b1){
    asm volatile("mma.sync.aligned.m16n8k32.row.col.s32.s8.s8.s32 "
                 "{%0,%1,%2,%3},{%4,%5,%6,%7},{%8,%9},{%0,%1,%2,%3};"
                 : "+r"(c[0]),"+r"(c[1]),"+r"(c[2]),"+r"(c[3])
                 : "r"(a0),"r"(a1),"r"(a2),"r"(a3),"r"(b0),"r"(b1));
}
static __device__ __forceinline__ float gelu_fast(float x){
    float z = fabsf(x)*0.70710678118654752f;
    float tt = __fdividef(1.0f, fmaf(0.3275911f, z, 1.0f));
    float poly = fmaf(fmaf(fmaf(fmaf(1.061405429f,tt,-1.453152027f),tt,1.421413741f),tt,-0.284496736f),tt,0.254829592f)*tt;
    float e = fmaf(-poly, __expf(-z*z), 1.0f);
    return 0.5f*x*(1.0f + copysignf(e, x));
}
static __device__ __forceinline__ uint32_t pack_h2(float a, float b){
    __half2 p = __floats2half2_rn(a,b); return *reinterpret_cast<uint32_t*>(&p);
}
static __device__ __forceinline__ unsigned short pack_s8x2(int a, int b){
    return (unsigned short)((a & 0xFF) | ((b & 0xFF) << 8));
}

// ---------------- prep kernels ----------------
__global__ void latconst_kernel(const float* __restrict__ emb, const int* __restrict__ traj,
                                const float* __restrict__ W1, const float* __restrict__ b1){
    int n = threadIdx.x;
    const float* e = emb + (size_t)traj[0]*128;
    float s = b1[n];
#pragma unroll 4
    for (int j = 0; j < 128; ++j) s = fmaf(e[j], W1[(size_t)(25+j)*256+n], s);
    g_latconst[n] = s;
}

// per-col scales: u = 126.5/colmax|fp16(W)| ; block l = layer (0:W1,1:W2,2:W3,3:W4,4:W5)
__global__ void prep_scales(const float* __restrict__ W1, const float* __restrict__ W2,
                            const float* __restrict__ W3, const float* __restrict__ W4,
                            const float* __restrict__ W5){
    int l = blockIdx.x, n = threadIdx.x;
    int cols = (l==4)?16:256;
    if (n >= cols) return;
    int K = (l==0)?25:256;
    int N = (l==4)?9:256;
    const float* W = (l==0)?W1:(l==1)?W2:(l==2)?W3:(l==3)?W4:W5;
    float m = 0.0f;
    if (!(l==4 && n>=9))
        for (int k = 0; k < K; ++k)
            m = fmaxf(m, fabsf(__half2float(__float2half_rn(W[(size_t)k*N+n]))));
    float u = 126.5f/fmaxf(m, 1e-30f);
    g_Wu[l*256+n] = u;
    g_Winvu[l*256+n] = 1.0f/u;
}

// chunk format (16KB): [0,8K) Wh fp16 [256n][16k] 32B rows ^((n&4)<<2);
//                      [8K,12K) Wl8 [256n][16k]; [12K,16K) Wh8
__global__ void prep_weights(const float* __restrict__ W1, const float* __restrict__ W2,
                             const float* __restrict__ W3, const float* __restrict__ W4,
                             const float* __restrict__ W5){
    int i = blockIdx.x*256 + threadIdx.x;            // 816 x 256 = 208896
    float v, u; unsigned char* base; uint32_t offH, off8;
    if (i < 196608) {                                // W2/3/4
        int l = i / 65536, r = i % 65536, k = r >> 8, n = r & 255;
        const float* W = (l==0)?W2:(l==1)?W3:W4;
        v = W[(size_t)k*256+n];
        u = g_Wu[(l+1)*256+n];
        base = g_W234img + (size_t)(l*16 + (k>>4))*16384u;
        int kl = k & 15;
        offH = (uint32_t)n*32u + (((uint32_t)(2*kl)) ^ (((uint32_t)n&4u)<<2));
        off8 = (uint32_t)n*16u + (uint32_t)kl;
    } else if (i < 204800) {                         // W1 (pad k>=25)
        int r = i-196608, n = r>>5, k = r&31;
        v = (k<25)? W1[(size_t)k*256+n] : 0.0f;
        u = g_Wu[n];
        base = g_W1img + (size_t)(k>>4)*16384u;
        int kl = k & 15;
        offH = (uint32_t)n*32u + (((uint32_t)(2*kl)) ^ (((uint32_t)n&4u)<<2));
        off8 = (uint32_t)n*16u + (uint32_t)kl;
    } else if (i < 208896) {                         // W5: [16n][256k], Wh 512B rows
        int r = i-204800, k = r>>4, n = r&15;
        v = (n<9)? W5[(size_t)k*9+n] : 0.0f;
        u = g_Wu[1024+n];
        base = g_W5img;
        offH = (uint32_t)n*512u + (((uint32_t)(2*k)) ^ (((uint32_t)n&7u)<<4));
        off8 = (uint32_t)n*256u + (uint32_t)k;
    } else return;
    __half hf = __float2half_rn(v);
    float hff = __half2float(hf);
    float wl = v - hff;
    int h8 = __float2int_rn(hff*u);
    int l8 = __float2int_rn(wl*u*2048.0f);
    *(__half*)(base + offH) = hf;
    *(signed char*)(base + 8192 + off8)  = (signed char)l8;
    *(signed char*)(base + 12288 + off8) = (signed char)h8;
}

// ---------------- chunk streaming (unchanged sizes) ----------------
static __device__ __forceinline__ void issue_u(uint32_t smb, int t, int u){
    if (u > 50) return;
    const unsigned char* s = (u < 2)  ? g_W1img + (size_t)u*16384
                           : (u < 50) ? g_W234img + (size_t)(u-2)*16384
                                      : g_W5img;
    uint32_t dst = smb + SWRING + (uint32_t)(u % 6)*16384u + (uint32_t)t*16u;
    const unsigned char* sp = s + (size_t)t*16;
#pragma unroll
    for (int i = 0; i < 4; ++i) cp16(dst + (uint32_t)i*4096u, sp + (size_t)i*4096);
}

// one k16 chunk: main fp16 MMA (fp32 acc) + fused int8 cross MMA (s32 acc)
static __device__ __forceinline__ void compute_chunk(const char* sm, int slot, int c,
        int wm, int wn, int g, int tig, float (&accF)[2][8][4], int (&accI)[2][8][4]){
    const uint32_t gx = (uint32_t)g << 4;
    const uint32_t wx = ((uint32_t)g & 4u) << 2;
    const int kb = c*32 + 4*tig;
    const uint32_t k0A = (uint32_t)kb ^ gx, k1A = (uint32_t)(kb+16) ^ gx;
    const uint32_t k0W = ((uint32_t)(4*tig)) ^ wx, k1W = ((uint32_t)(4*tig+16)) ^ wx;
    const uint32_t a8off = (uint32_t)(c*16 + 4*tig);
    uint32_t ah[2][4], q[2][4];
#pragma unroll
    for (int mt=0; mt<2; ++mt){
        int r = wm*32 + mt*16 + g;
        const char* abh = sm + SAH + r*512;
        ah[mt][0]=*(const uint32_t*)(abh+k0A); ah[mt][1]=*(const uint32_t*)(abh+4096+k0A);
        ah[mt][2]=*(const uint32_t*)(abh+k1A); ah[mt][3]=*(const uint32_t*)(abh+4096+k1A);
        const char* a8h = sm + SA8H + r*272;
        const char* a8l = sm + SA8L + r*272;
        q[mt][0]=*(const uint32_t*)(a8h+a8off); q[mt][1]=*(const uint32_t*)(a8h+2176+a8off);
        q[mt][2]=*(const uint32_t*)(a8l+a8off); q[mt][3]=*(const uint32_t*)(a8l+2176+a8off);
    }
    const char* wbase = sm + slot + (wn*64 + g)*32;
    const char* w8base = sm + slot + 8192 + (wn*64 + g)*16;
#pragma unroll
    for (int nt=0; nt<8; ++nt){
        const char* wbh = wbase + nt*256;
        uint32_t bh0=*(const uint32_t*)(wbh+k0W), bh1=*(const uint32_t*)(wbh+k1W);
        const char* w8 = w8base + nt*128;
        uint32_t bl8=*(const uint32_t*)(w8 + 4*tig);
        uint32_t bh8=*(const uint32_t*)(w8 + 4096 + 4*tig);
#pragma unroll
        for (int mt=0; mt<2; ++mt){
            mma16816(accF[mt][nt], ah[mt][0],ah[mt][1],ah[mt][2],ah[mt][3], bh0,bh1);
            mma_s8 (accI[mt][nt], q[mt][0],q[mt][1],q[mt][2],q[mt][3], bl8,bh8);
        }
    }
}

static __device__ __forceinline__ void epilogue_layer(char* sm, int L,
        int wm, int wn, int g, int tig, float (&accF)[2][8][4], int (&accI)[2][8][4]){
    const uint32_t gx = (uint32_t)g << 4;
    float* SR  = (float*)(sm + SROWP);
    float* SM4 = (float*)(sm + SMAXS);
    const float* IVU  = (const float*)(sm + SWU + L*1024);
    const float* bias = (const float*)(sm + SBIAS + L*1024);
    const int rowb = wm*32 + g;
    float ivp[4];
    ivp[0]=SR[rowb]*(1.0f/2048.0f);    ivp[1]=SR[rowb+8]*(1.0f/2048.0f);
    ivp[2]=SR[rowb+16]*(1.0f/2048.0f); ivp[3]=SR[rowb+24]*(1.0f/2048.0f);
    float rm[4] = {0,0,0,0};
#pragma unroll
    for (int mt=0; mt<2; ++mt){
        char* rbh = sm + SAH + (rowb + mt*16)*512;
#pragma unroll
        for (int nt=0; nt<8; ++nt){
            int n0 = wn*64 + nt*8 + 2*tig;
            float u0 = IVU[n0], u1 = IVU[n0+1];
            float* cf = accF[mt][nt]; int* ci = accI[mt][nt];
            float x0 = cf[0] + (float)ci[0]*ivp[mt*2]*u0   + bias[n0];
            float x1 = cf[1] + (float)ci[1]*ivp[mt*2]*u1   + bias[n0+1];
            float x2 = cf[2] + (float)ci[2]*ivp[mt*2+1]*u0 + bias[n0];
            float x3 = cf[3] + (float)ci[3]*ivp[mt*2+1]*u1 + bias[n0+1];
            float y0=gelu_fast(x0), y1=gelu_fast(x1), y2=gelu_fast(x2), y3=gelu_fast(x3);
            cf[0]=y0; cf[1]=y1; cf[2]=y2; cf[3]=y3;
            rm[mt*2]   = fmaxf(rm[mt*2],   fmaxf(fabsf(y0),fabsf(y1)));
            rm[mt*2+1] = fmaxf(rm[mt*2+1], fmaxf(fabsf(y2),fabsf(y3)));
            uint32_t kb2 = ((uint32_t)(n0*2)) ^ gx;
            *(uint32_t*)(rbh + kb2)        = pack_h2(y0,y1);
            *(uint32_t*)(rbh + 4096 + kb2) = pack_h2(y2,y3);
        }
    }
#pragma unroll
    for (int i=0;i<4;++i){
        rm[i] = fmaxf(rm[i], __shfl_xor_sync(0xFFFFFFFFu, rm[i], 1));
        rm[i] = fmaxf(rm[i], __shfl_xor_sync(0xFFFFFFFFu, rm[i], 2));
    }
    if (tig == 0){
#pragma unroll
        for (int i=0;i<4;++i) SM4[(rowb + i*8)*4 + wn] = rm[i];
    }
    __syncthreads();
    float pq[4];
#pragma unroll
    for (int i=0;i<4;++i){
        int row = rowb + i*8;
        float m4 = fmaxf(fmaxf(SM4[row*4+0],SM4[row*4+1]),fmaxf(SM4[row*4+2],SM4[row*4+3]));
        pq[i] = 126.5f/fmaxf(m4, 1e-30f);
        if (tig==0 && wn==0) SR[row] = 1.0f/pq[i];
    }
#pragma unroll
    for (int mt=0; mt<2; ++mt){
        char* dH = sm + SA8H + (rowb + mt*16)*272;
        char* dL = sm + SA8L + (rowb + mt*16)*272;
        float p0 = pq[mt*2], p1 = pq[mt*2+1];
#pragma unroll
        for (int nt=0; nt<8; ++nt){
            int n0 = wn*64 + nt*8 + 2*tig;
            float* cf = accF[mt][nt];
            float h0 = __half2float(__float2half_rn(cf[0]));
            float h1 = __half2float(__float2half_rn(cf[1]));
            float h2 = __half2float(__float2half_rn(cf[2]));
            float h3 = __half2float(__float2half_rn(cf[3]));
            int a0 = __float2int_rn(h0*p0), a1 = __float2int_rn(h1*p0);
            int a2 = __float2int_rn(h2*p1), a3 = __float2int_rn(h3*p1);
            int l0 = __float2int_rn((cf[0]-h0)*p0*2048.0f), l1 = __float2int_rn((cf[1]-h1)*p0*2048.0f);
            int l2 = __float2int_rn((cf[2]-h2)*p1*2048.0f), l3 = __float2int_rn((cf[3]-h3)*p1*2048.0f);
            *(unsigned short*)(dH + n0)        = pack_s8x2(a0,a1);
            *(unsigned short*)(dH + 2176 + n0) = pack_s8x2(a2,a3);
            *(unsigned short*)(dL + n0)        = pack_s8x2(l0,l1);
            *(unsigned short*)(dL + 2176 + n0) = pack_s8x2(l2,l3);
        }
    }
}

// ---------------- main kernel: 64 particles / CTA, 256 threads ----------------
__global__ void __launch_bounds__(256, 1)
mlp_kernel(const float* __restrict__ Fg, const float* __restrict__ Cg,
           const float* __restrict__ b2, const float* __restrict__ b3,
           const float* __restrict__ b4, const float* __restrict__ b5,
           float* __restrict__ outg, int B){
    extern __shared__ char sm[];
    const uint32_t smb = smem_u32(sm);
    const int t = threadIdx.x, w = t>>5, lane = t&31;
    const int g = lane>>2, tig = lane&3;
    const int wm = w>>2, wn = w&3;
    const int g0 = blockIdx.x*64;

    // ---- prologue: chunks 0..3; biases + invu with group 0 ----
    issue_u(smb, t, 0);
    {
        const char* src;
        switch (t >> 6){
            case 0:  src = (const char*)g_latconst; break;
            case 1:  src = (const char*)b2; break;
            case 2:  src = (const char*)b3; break;
            default: src = (const char*)b4; break;
        }
        cp16(smb + SBIAS + (uint32_t)t*16u, src + (size_t)(t & 63)*16);
        for (int i = t; i < 320; i += 256)
            cp16(smb + SWU + (uint32_t)i*16u, (const char*)g_Winvu + (size_t)i*16);
    }
    CP_COMMIT();
    issue_u(smb, t, 1); CP_COMMIT();
    issue_u(smb, t, 2); CP_COMMIT();
    issue_u(smb, t, 3); CP_COMMIT();

    // ---- phase 1: features into A (fp16 + int8 digits) + polar rotation ----
    float R0=0,R1=0,R2=0,R3=0,R4=0,R5=0,R6=0,R7=0,R8=0;
    float F0=0,F1=0,F2=0,F3=0,F4=0,F5=0,F6=0,F7=0,F8=0;
    if (t < 64){
        int gp = g0 + t;
        float feat[25];
#pragma unroll
        for (int i=0;i<25;++i) feat[i]=0.0f;
        if (gp < B){
            const float* Fp = Fg + (size_t)gp*9;
            F0=Fp[0];F1=Fp[1];F2=Fp[2];F3=Fp[3];F4=Fp[4];F5=Fp[5];F6=Fp[6];F7=Fp[7];F8=Fp[8];
            float M00=F0*F0+F3*F3+F6*F6, M01=F0*F1+F3*F4+F6*F7, M02=F0*F2+F3*F5+F6*F8;
            float M11=F1*F1+F4*F4+F7*F7, M12=F1*F2+F4*F5+F7*F8, M22=F2*F2+F5*F5+F8*F8;
            float det = F0*(F4*F8-F5*F7) - F1*(F3*F8-F5*F6) + F2*(F3*F7-F4*F6);
            float q=(M00+M11+M22)*(1.0f/3.0f);
            float p1=M01*M01+M02*M02+M12*M12;
            float d0=M00-q,d1=M11-q,d2=M22-q;
            float p=sqrtf((d0*d0+d1*d1+d2*d2+2.0f*p1)*(1.0f/6.0f)+1e-30f);
            float ip=1.0f/p;
            float B00=d0*ip,B01=M01*ip,B02=M02*ip,B11=d1*ip,B12=M12*ip,B22=d2*ip;
            float detB=B00*(B11*B22-B12*B12)-B01*(B01*B22-B12*B02)+B02*(B01*B12-B11*B02);
            float rr=fminf(1.0f,fmaxf(-1.0f,0.5f*detB));
            float phi=acosf(rr)*(1.0f/3.0f);
            float e1=q+2.0f*p*cosf(phi);
            float e3=q+2.0f*p*cosf(phi+2.0943951023931953f);
            float e2=3.0f*q-e1-e3;
            float f00=fmaxf(F0,EPSV);
            feat[0]=sqrtf(fmaxf(e1,0.0f))-1.0f; feat[1]=sqrtf(fmaxf(e2,0.0f))-1.0f; feat[2]=sqrtf(fmaxf(e3,0.0f))-1.0f;
            feat[3]=M00-1.0f; feat[4]=M01; feat[5]=M02; feat[6]=M01; feat[7]=M11-1.0f; feat[8]=M12;
            feat[9]=M02; feat[10]=M12; feat[11]=M22-1.0f;
            feat[12]=det-1.0f; feat[13]=logf(det)-1.0f; feat[14]=f00-1.0f; feat[15]=logf(f00)-1.0f;
            const float* Cp = Cg + (size_t)gp*9;
#pragma unroll
            for (int i=0;i<9;++i) feat[16+i]=Cp[i];
            float X0=F0,X1=F1,X2=F2,X3=F3,X4=F4,X5=F5,X6=F6,X7=F7,X8=F8;
#pragma unroll
            for (int it=0; it<4; ++it){
                float C00=X4*X8-X5*X7, C01=-(X3*X8-X5*X6), C02=X3*X7-X4*X6;
                float C10=-(X1*X8-X2*X7), C11=X0*X8-X2*X6, C12=-(X0*X7-X1*X6);
                float C20=X1*X5-X2*X4, C21=-(X0*X5-X2*X3), C22=X0*X4-X1*X3;
                float h = 0.5f/(X0*C00+X1*C01+X2*C02);
                X0=0.5f*X0+C00*h; X1=0.5f*X1+C01*h; X2=0.5f*X2+C02*h;
                X3=0.5f*X3+C10*h; X4=0.5f*X4+C11*h; X5=0.5f*X5+C12*h;
                X6=0.5f*X6+C20*h; X7=0.5f*X7+C21*h; X8=0.5f*X8+C22*h;
            }
            R0=X0;R1=X1;R2=X2;R3=X3;R4=X4;R5=X5;R6=X6;R7=X7;R8=X8;
        }
        float rmx = 0.0f;
#pragma unroll
        for (int i=0;i<25;++i) rmx = fmaxf(rmx, fabsf(feat[i]));
        float pf = 126.5f/fmaxf(rmx, 1e-30f);
        ((float*)(sm + SROWP))[t] = 1.0f/pf;
        uint32_t mx = ((uint32_t)t & 7u) << 4;
        char* frh = sm + SAH + t*512;
        char* d8h = sm + SA8H + t*272;
        char* d8l = sm + SA8L + t*272;
#pragma unroll
        for (int j=0;j<16;++j){
            float x0 = (2*j   < 25)? feat[2*j]   : 0.0f;
            float x1 = (2*j+1 < 25)? feat[2*j+1] : 0.0f;
            *(uint32_t*)(frh + (((uint32_t)(4*j)) ^ mx)) = pack_h2(x0, x1);
            float h0 = __half2float(__float2half_rn(x0));
            float h1 = __half2float(__float2half_rn(x1));
            int a0 = __float2int_rn(h0*pf), a1 = __float2int_rn(h1*pf);
            int l0 = __float2int_rn((x0-h0)*pf*2048.0f), l1 = __float2int_rn((x1-h1)*pf*2048.0f);
            *(unsigned short*)(d8h + 2*j) = pack_s8x2(a0,a1);
            *(unsigned short*)(d8l + 2*j) = pack_s8x2(l0,l1);
        }
    }

    // ---- layers 1..4: 50-chunk stream, depth-4 pipeline ----
    int u = 0;
#pragma unroll 1
    for (int L = 0; L < 4; ++L){
        const int nc = (L == 0) ? 2 : 16;
        float accF[2][8][4];
        int accI[2][8][4];
#pragma unroll
        for (int mt=0;mt<2;++mt)
#pragma unroll
            for (int nt=0;nt<8;++nt){
#pragma unroll
                for (int j=0;j<4;++j){ accF[mt][nt][j]=0.0f; accI[mt][nt][j]=0; }
            }
#pragma unroll 1
        for (int c = 0; c < nc; ++c, ++u){
            issue_u(smb, t, u+4);
            CP_COMMIT();
            CP_WAIT4();
            __syncthreads();
            compute_chunk(sm, SWRING + (u % 6)*16384, c, wm, wn, g, tig, accF, accI);
        }
        __syncthreads();                       // all reads of A done
        epilogue_layer(sm, L, wm, wn, g, tig, accF, accI);
        __syncthreads();                       // digits visible before next layer reads
    }

    // ---- L5: chunk 50 (W5), warps 0..3 ----
    CP_WAIT0();
    __syncthreads();
    {
        const int slot = SWRING + (50 % 6)*16384;
        if (w < 4){
            float aF[2][4]; int aI[2][4];
#pragma unroll
            for (int nt=0;nt<2;++nt)
#pragma unroll
                for (int j=0;j<4;++j){ aF[nt][j]=0.0f; aI[nt][j]=0; }
            int m0 = w*16 + g;
            const char* abh = sm + SAH + m0*512;
            const char* a8h = sm + SA8H + m0*272;
            const char* a8l = sm + SA8L + m0*272;
            uint32_t gx = (uint32_t)g<<4;
#pragma unroll
            for (int kc=0; kc<16; ++kc){
                int kb = kc*32 + 4*tig;
                uint32_t k0 = (uint32_t)kb ^ gx, k1 = (uint32_t)(kb+16) ^ gx;
                uint32_t ah0=*(const uint32_t*)(abh+k0), ah1=*(const uint32_t*)(abh+4096+k0);
                uint32_t ah2=*(const uint32_t*)(abh+k1), ah3=*(const uint32_t*)(abh+4096+k1);
                uint32_t q0=*(const uint32_t*)(a8h + kc*16 + 4*tig);
                uint32_t q1=*(const uint32_t*)(a8h + 2176 + kc*16 + 4*tig);
                uint32_t q2=*(const uint32_t*)(a8l + kc*16 + 4*tig);
                uint32_t q3=*(const uint32_t*)(a8l + 2176 + kc*16 + 4*tig);
#pragma unroll
                for (int nt=0; nt<2; ++nt){
                    int n = nt*8 + g;
                    const char* wbh = sm + slot + n*512;
                    uint32_t bh0=*(const uint32_t*)(wbh+k0), bh1=*(const uint32_t*)(wbh+k1);
                    uint32_t bl8=*(const uint32_t*)(sm + slot + 8192  + n*256 + kc*16 + 4*tig);
                    uint32_t bh8=*(const uint32_t*)(sm + slot + 12288 + n*256 + kc*16 + 4*tig);
                    mma16816(aF[nt], ah0,ah1,ah2,ah3, bh0,bh1);
                    mma_s8 (aI[nt], q0,q1,q2,q3, bl8,bh8);
                }
            }
            const float* SR = (const float*)(sm + SROWP);
            const float* IVU5 = (const float*)(sm + SWU + 4*1024);
            float iv0 = SR[m0]*(1.0f/2048.0f), iv1 = SR[m0+8]*(1.0f/2048.0f);
#pragma unroll
            for (int nt=0; nt<2; ++nt){
                int n0 = nt*8 + 2*tig;
                float u0 = IVU5[n0], u1 = IVU5[n0+1];
                float v0 = aF[nt][0] + (float)aI[nt][0]*iv0*u0;
                float v1 = aF[nt][1] + (float)aI[nt][1]*iv0*u1;
                float v2 = aF[nt][2] + (float)aI[nt][2]*iv1*u0;
                float v3 = aF[nt][3] + (float)aI[nt][3]*iv1*u1;
                *(float2*)(sm + SD + ((size_t)m0*18 + n0)*4)     = make_float2(v0, v1);
                *(float2*)(sm + SD + ((size_t)(m0+8)*18 + n0)*4) = make_float2(v2, v3);
            }
        }
    }
    __syncthreads();

    // ---- final epilogue: symmetrize, P = R x, cauchy = P F^T ----
    if (t < 64){
        int gp = g0 + t;
        if (gp < B){
            const float* dr = (const float*)(sm + SD + (size_t)t*72);
            float o[9];
#pragma unroll
            for (int j=0;j<9;++j) o[j] = dr[j] + b5[j];
            float x00=o[0], x11=o[4], x22=o[8];
            float x01=0.5f*(o[1]+o[3]), x02=0.5f*(o[2]+o[6]), x12=0.5f*(o[5]+o[7]);
            float P00=R0*x00+R1*x01+R2*x02, P01=R0*x01+R1*x11+R2*x12, P02=R0*x02+R1*x12+R2*x22;
            float P10=R3*x00+R4*x01+R5*x02, P11=R3*x01+R4*x11+R5*x12, P12=R3*x02+R4*x12+R5*x22;
            float P20=R6*x00+R7*x01+R8*x02, P21=R6*x01+R7*x11+R8*x12, P22=R6*x02+R7*x12+R8*x22;
            float* op = outg + (size_t)gp*9;
            op[0]=P00*F0+P01*F1+P02*F2; op[1]=P00*F3+P01*F4+P02*F5; op[2]=P00*F6+P01*F7+P02*F8;
            op[3]=P10*F0+P11*F1+P12*F2; op[4]=P10*F3+P11*F4+P12*F5; op[5]=P10*F6+P11*F7+P12*F8;
            op[6]=P20*F0+P21*F1+P22*F2; op[7]=P20*F3+P21*F4+P22*F5; op[8]=P20*F6+P21*F7+P22*F8;
        }
    }
}

// ---------------------------------------------------------------------------
extern "C" void kernel_launch(void* const* d_in, const int* in_sizes, int n_in,
                              void* d_out, int out_size){
    const float* F   = (const float*)d_in[0];
    const float* C   = (const float*)d_in[1];
    const float* emb = (const float*)d_in[2];
    const int* traj  = (const int*)d_in[3];
    const float* W1 = (const float*)d_in[4];  const float* b1 = (const float*)d_in[5];
    const float* W2 = (const float*)d_in[6];  const float* b2 = (const float*)d_in[7];
    const float* W3 = (const float*)d_in[8];  const float* b3 = (const float*)d_in[9];
    const float* W4 = (const float*)d_in[10]; const float* b4 = (const float*)d_in[11];
    const float* W5 = (const float*)d_in[12]; const float* b5 = (const float*)d_in[13];
    int B = in_sizes[0] / 9;

    latconst_kernel<<<1, 256>>>(emb, traj, W1, b1);
    prep_scales<<<5, 256>>>(W1, W2, W3, W4, W5);
    prep_weights<<<816, 256>>>(W1, W2, W3, W4, W5);

    cudaFuncSetAttribute(mlp_kernel, cudaFuncAttributeMaxDynamicSharedMemorySize, SM_TOTAL);
    int grid = (B + 63) / 64;
    mlp_kernel<<<grid, 256, SM_TOTAL>>>(F, C, b2, b3, b4, b5, (float*)d_out, B);
}